// round 1
// baseline (speedup 1.0000x reference)
#include <cuda_runtime.h>
#include <cstddef>

#define NN 2048
#define DM 128
#define HH 8
#define DH 16
#define ED 8

#define BI 16
#define TJ 32
#define KSTR 20   // padded row stride (floats) for K/V smem tiles

// ---------- device scratch (no allocations allowed) ----------
__device__ float g_wer[ED * DM];        // (We@Wr)[e][h*16+d]
__device__ float g_Q  [NN * DM];        // Q row-major [i][128]
__device__ float g_Kh [NN * DM];        // K head-major [h][j][16]
__device__ float g_Vh [NN * DM];        // V head-major [h][j][16]
__device__ float g_QW [NN * HH * ED];   // QW [i][h*8+e]
__device__ float g_O  [NN * DM];        // attention output [i][128]

// ---------- kernel 1: Wer = We @ Wr (tiny) ----------
__global__ void wer_kernel(const float* __restrict__ We, const float* __restrict__ Wr) {
    int c = threadIdx.x;  // 0..127
    for (int e = 0; e < ED; e++) {
        float s = 0.f;
        #pragma unroll 8
        for (int k = 0; k < 32; k++) s += We[e * 32 + k] * Wr[k * DM + c];
        g_wer[e * DM + c] = s;
    }
}

// ---------- kernel 2: projections Q,K,V + QW ----------
__global__ void proj_kernel(const float* __restrict__ X,
                            const float* __restrict__ Wq,
                            const float* __restrict__ Wk,
                            const float* __restrict__ Wv) {
    __shared__ float xs[4][DM];
    __shared__ float qs[4][DM];
    const int i0 = blockIdx.x * 4;
    const int c = threadIdx.x;  // 0..127

    #pragma unroll
    for (int r = 0; r < 4; r++) xs[r][c] = X[(i0 + r) * DM + c];
    __syncthreads();

    float qa[4] = {0.f, 0.f, 0.f, 0.f};
    float ka[4] = {0.f, 0.f, 0.f, 0.f};
    float va[4] = {0.f, 0.f, 0.f, 0.f};
    for (int d = 0; d < DM; d++) {
        float wq = Wq[d * DM + c];
        float wk = Wk[d * DM + c];
        float wv = Wv[d * DM + c];
        #pragma unroll
        for (int r = 0; r < 4; r++) {
            float x = xs[r][d];
            qa[r] += x * wq;
            ka[r] += x * wk;
            va[r] += x * wv;
        }
    }
    const int h = c >> 4, d = c & 15;
    #pragma unroll
    for (int r = 0; r < 4; r++) {
        g_Q[(i0 + r) * DM + c] = qa[r];
        qs[r][c] = qa[r];
        g_Kh[(h * NN + i0 + r) * DH + d] = ka[r];
        g_Vh[(h * NN + i0 + r) * DH + d] = va[r];
    }
    __syncthreads();
    if (c < 64) {
        const int hh = c >> 3, e = c & 7;
        #pragma unroll
        for (int r = 0; r < 4; r++) {
            float s = 0.f;
            #pragma unroll
            for (int dd = 0; dd < DH; dd++)
                s += qs[r][hh * DH + dd] * g_wer[e * DM + hh * DH + dd];
            g_QW[(i0 + r) * 64 + c] = s;
        }
    }
}

// ---------- kernel 3: fused attention (all heads per block) ----------
__global__ __launch_bounds__(512)
void attn_kernel(const int* __restrict__ adj, const float* __restrict__ edge) {
    extern __shared__ float sm[];
    float* Qs   = sm;                       // 16*128 = 2048
    float* QWs  = Qs + BI * DM;             // 16*64  = 1024
    float* sc   = QWs + BI * 64;            // 8*16*32 = 4096
    float* Ks   = sc + HH * BI * TJ;        // 8*32*20 = 5120
    float* Vs   = Ks + HH * TJ * KSTR;      // 5120
    int*   adjs = (int*)(Vs + HH * TJ * KSTR);  // 512
    float* lred = (float*)(adjs + BI * TJ);     // 512
    float* red  = Ks;                       // aliases Ks(+Vs) for final reduction

    const int tid = threadIdx.x;
    const int i0 = blockIdx.x * BI;

    for (int t = tid; t < BI * DM; t += 512) Qs[t] = g_Q[i0 * DM + t];
    for (int t = tid; t < BI * 64; t += 512) QWs[t] = g_QW[i0 * 64 + t];

    // phase-role ids
    const int p1_i = tid >> 5, p1_j = tid & 31;                     // (i, j) pair
    const int p2_h = tid >> 6, p2_j = (tid >> 1) & 31, p2_ih = tid & 1;
    const int p3_h = tid >> 6, p3_iq = (tid >> 4) & 3,
              p3_dq = (tid >> 2) & 3, p3_jq = tid & 3;

    float acc[4][4];
    #pragma unroll
    for (int a = 0; a < 4; a++)
        #pragma unroll
        for (int b = 0; b < 4; b++) acc[a][b] = 0.f;
    float lp[4] = {0.f, 0.f, 0.f, 0.f};

    __syncthreads();

    for (int jt = 0; jt < NN; jt += TJ) {
        // ---- stage K, V tiles (float4) + adj ----
        {
            const float4* K4 = (const float4*)g_Kh;
            const float4* V4 = (const float4*)g_Vh;
            #pragma unroll
            for (int t4 = tid; t4 < HH * TJ * 4; t4 += 512) {
                int h = t4 >> 7, jj = (t4 >> 2) & 31, d4 = t4 & 3;
                float4 kv = K4[h * (NN * 4) + (jt + jj) * 4 + d4];
                *(float4*)&Ks[(h * TJ + jj) * KSTR + d4 * 4] = kv;
                float4 vv = V4[h * (NN * 4) + (jt + jj) * 4 + d4];
                *(float4*)&Vs[(h * TJ + jj) * KSTR + d4 * 4] = vv;
            }
            adjs[tid] = adj[(size_t)(i0 + (tid >> 5)) * NN + jt + (tid & 31)];
        }
        __syncthreads();

        // ---- phase 1: edge bias for all 8 heads (one thread per (i,j)) ----
        {
            const float4* ep = (const float4*)(edge +
                ((size_t)(i0 + p1_i) * NN + (size_t)(jt + p1_j)) * ED);
            float4 e0 = ep[0], e1 = ep[1];
            const float* qw = QWs + p1_i * 64;
            #pragma unroll
            for (int h = 0; h < 8; h++) {
                float b = qw[h*8+0]*e0.x + qw[h*8+1]*e0.y + qw[h*8+2]*e0.z + qw[h*8+3]*e0.w
                        + qw[h*8+4]*e1.x + qw[h*8+5]*e1.y + qw[h*8+6]*e1.z + qw[h*8+7]*e1.w;
                sc[(h * BI + p1_i) * TJ + p1_j] = b;
            }
        }
        __syncthreads();

        // ---- phase 2: QK + leaky-relu + mask + exp ----
        {
            const float4* kp = (const float4*)&Ks[(p2_h * TJ + p2_j) * KSTR];
            float4 k0 = kp[0], k1 = kp[1], k2 = kp[2], k3 = kp[3];
            #pragma unroll
            for (int ii = 0; ii < 8; ii++) {
                int i = p2_ih * 8 + ii;
                const float4* qp = (const float4*)&Qs[i * DM + p2_h * DH];
                float4 q0 = qp[0], q1 = qp[1], q2 = qp[2], q3 = qp[3];
                float s = q0.x*k0.x + q0.y*k0.y + q0.z*k0.z + q0.w*k0.w
                        + q1.x*k1.x + q1.y*k1.y + q1.z*k1.z + q1.w*k1.w
                        + q2.x*k2.x + q2.y*k2.y + q2.z*k2.z + q2.w*k2.w
                        + q3.x*k3.x + q3.y*k3.y + q3.z*k3.z + q3.w*k3.w;
                int idx = (p2_h * BI + i) * TJ + p2_j;
                s = (s + sc[idx]) * 0.25f;                 // /sqrt(16)
                s = (s > 0.f) ? s : 0.2f * s;              // leaky relu
                float p = (adjs[i * TJ + p2_j] != 0) ? __expf(s) : 0.f;
                sc[idx] = p;
            }
        }
        __syncthreads();

        // ---- phase 3: accumulate P @ V ----
        {
            #pragma unroll
            for (int jj = 0; jj < 8; jj++) {
                int j = p3_jq * 8 + jj;
                float4 v = *(const float4*)&Vs[(p3_h * TJ + j) * KSTR + p3_dq * 4];
                #pragma unroll
                for (int ii = 0; ii < 4; ii++) {
                    float p = sc[(p3_h * BI + p3_iq * 4 + ii) * TJ + j];
                    acc[ii][0] += p * v.x;
                    acc[ii][1] += p * v.y;
                    acc[ii][2] += p * v.z;
                    acc[ii][3] += p * v.w;
                    if (p3_dq == 0) lp[ii] += p;
                }
            }
        }
        __syncthreads();
    }

    // ---- final reductions across jq slices ----
    if (p3_dq == 0) {
        #pragma unroll
        for (int ii = 0; ii < 4; ii++)
            lred[(p3_h * BI + p3_iq * 4 + ii) * 4 + p3_jq] = lp[ii];
    }
    #pragma unroll
    for (int ii = 0; ii < 4; ii++)
        #pragma unroll
        for (int dd = 0; dd < 4; dd++)
            red[tid * 16 + ii * 4 + dd] = acc[ii][dd];
    __syncthreads();

    if (p3_jq == 0) {
        #pragma unroll
        for (int ii = 0; ii < 4; ii++) {
            int i = p3_iq * 4 + ii;
            int lb = (p3_h * BI + i) * 4;
            float li = lred[lb + 0] + lred[lb + 1] + lred[lb + 2] + lred[lb + 3];
            float inv = 1.f / li;
            #pragma unroll
            for (int dd = 0; dd < 4; dd++) {
                float s = red[(tid + 0) * 16 + ii * 4 + dd]
                        + red[(tid + 1) * 16 + ii * 4 + dd]
                        + red[(tid + 2) * 16 + ii * 4 + dd]
                        + red[(tid + 3) * 16 + ii * 4 + dd];
                g_O[(size_t)(i0 + i) * DM + p3_h * DH + p3_dq * 4 + dd] = s * inv;
            }
        }
    }
}

// ---------- kernel 4: out = O @ Wo ----------
__global__ void outproj_kernel(const float* __restrict__ Wo, float* __restrict__ out) {
    __shared__ float xs[4][DM];
    const int i0 = blockIdx.x * 4;
    const int c = threadIdx.x;
    #pragma unroll
    for (int r = 0; r < 4; r++) xs[r][c] = g_O[(i0 + r) * DM + c];
    __syncthreads();
    float a[4] = {0.f, 0.f, 0.f, 0.f};
    for (int d = 0; d < DM; d++) {
        float w = Wo[d * DM + c];
        #pragma unroll
        for (int r = 0; r < 4; r++) a[r] += xs[r][d] * w;
    }
    #pragma unroll
    for (int r = 0; r < 4; r++) out[(i0 + r) * DM + c] = a[r];
}

// ---------- launch ----------
extern "C" void kernel_launch(void* const* d_in, const int* in_sizes, int n_in,
                              void* d_out, int out_size) {
    const float* X    = (const float*)d_in[0];
    const int*   adj  = (const int*)  d_in[1];
    const float* edge = (const float*)d_in[2];
    const float* Wq   = (const float*)d_in[3];
    const float* Wk   = (const float*)d_in[4];
    const float* Wv   = (const float*)d_in[5];
    const float* We   = (const float*)d_in[6];
    const float* Wr   = (const float*)d_in[7];
    const float* Wo   = (const float*)d_in[8];
    float* out = (float*)d_out;

    const int smem_bytes = (BI*DM + BI*64 + HH*BI*TJ + 2*HH*TJ*KSTR + BI*TJ + 512) * 4;
    cudaFuncSetAttribute(attn_kernel, cudaFuncAttributeMaxDynamicSharedMemorySize, smem_bytes);

    wer_kernel<<<1, 128>>>(We, Wr);
    proj_kernel<<<NN / 4, 128>>>(X, Wq, Wk, Wv);
    attn_kernel<<<NN / BI, 512, smem_bytes>>>(adj, edge);
    outproj_kernel<<<NN / 4, 128>>>(Wo, out);
}

// round 2
// speedup vs baseline: 1.0302x; 1.0302x over previous
#include <cuda_runtime.h>
#include <cstddef>

#define NN 2048
#define DM 128
#define HH 8
#define DH 16
#define ED 8

#define BI 16
#define TJ 32
#define KSTR 20      // padded row stride (floats) for K/V smem tiles
#define NSPLIT 16    // j-range splits (grid.y)
#define JT_PER (NN / (TJ * NSPLIT))   // 4 tiles per block

// ---------- packed f32x2 helpers (sm_103a FFMA2) ----------
using u64 = unsigned long long;
__device__ __forceinline__ u64 f2_pack(float lo, float hi) {
    u64 r; asm("mov.b64 %0, {%1,%2};" : "=l"(r) : "f"(lo), "f"(hi)); return r;
}
__device__ __forceinline__ u64 f2_mul(u64 a, u64 b) {
    u64 d; asm("mul.rn.f32x2 %0, %1, %2;" : "=l"(d) : "l"(a), "l"(b)); return d;
}
__device__ __forceinline__ u64 f2_fma(u64 a, u64 b, u64 c) {
    u64 d; asm("fma.rn.f32x2 %0, %1, %2, %3;" : "=l"(d) : "l"(a), "l"(b), "l"(c)); return d;
}
__device__ __forceinline__ u64 f2_add(u64 a, u64 b) {
    u64 d; asm("add.rn.f32x2 %0, %1, %2;" : "=l"(d) : "l"(a), "l"(b)); return d;
}
__device__ __forceinline__ float f2_red(u64 a) {
    float lo, hi; asm("mov.b64 {%0,%1}, %2;" : "=f"(lo), "=f"(hi) : "l"(a)); return lo + hi;
}
__device__ __forceinline__ void f2_unpack(u64 a, float& lo, float& hi) {
    asm("mov.b64 {%0,%1}, %2;" : "=f"(lo), "=f"(hi) : "l"(a));
}

// ---------- device scratch ----------
__device__ float g_wer[ED * DM];
__device__ float g_Q  [NN * DM];
__device__ float g_Kh [NN * DM];            // head-major [h][j][16]
__device__ float g_Vh [NN * DM];
__device__ float g_QW [NN * HH * ED];       // [i][h*8+e]
__device__ float g_part[NSPLIT * NN * DM];  // unnormalized partial PV sums
__device__ float g_lsum[NSPLIT * NN * HH];  // partial softmax denominators

// ---------- kernel 1: Wer = We @ Wr ----------
__global__ void wer_kernel(const float* __restrict__ We, const float* __restrict__ Wr) {
    int c = threadIdx.x;
    for (int e = 0; e < ED; e++) {
        float s = 0.f;
        #pragma unroll 8
        for (int k = 0; k < 32; k++) s += We[e * 32 + k] * Wr[k * DM + c];
        g_wer[e * DM + c] = s;
    }
}

// ---------- kernel 2: projections Q,K,V + QW (8 rows / block) ----------
__global__ __launch_bounds__(128)
void proj_kernel(const float* __restrict__ X,
                 const float* __restrict__ Wq,
                 const float* __restrict__ Wk,
                 const float* __restrict__ Wv) {
    __shared__ float xs[8][DM];
    __shared__ float qs[8][DM];
    const int i0 = blockIdx.x * 8;
    const int c = threadIdx.x;

    #pragma unroll
    for (int r = 0; r < 8; r++) xs[r][c] = X[(i0 + r) * DM + c];
    __syncthreads();

    float qa[8], ka[8], va[8];
    #pragma unroll
    for (int r = 0; r < 8; r++) { qa[r] = 0.f; ka[r] = 0.f; va[r] = 0.f; }
    for (int d = 0; d < DM; d++) {
        float wq = Wq[d * DM + c];
        float wk = Wk[d * DM + c];
        float wv = Wv[d * DM + c];
        #pragma unroll
        for (int r = 0; r < 8; r++) {
            float x = xs[r][d];
            qa[r] += x * wq;
            ka[r] += x * wk;
            va[r] += x * wv;
        }
    }
    const int h = c >> 4, d = c & 15;
    #pragma unroll
    for (int r = 0; r < 8; r++) {
        g_Q[(i0 + r) * DM + c] = qa[r];
        qs[r][c] = qa[r];
        g_Kh[(h * NN + i0 + r) * DH + d] = ka[r];
        g_Vh[(h * NN + i0 + r) * DH + d] = va[r];
    }
    __syncthreads();
    if (c < 64) {
        const int hh = c >> 3, e = c & 7;
        #pragma unroll
        for (int r = 0; r < 8; r++) {
            float s = 0.f;
            #pragma unroll
            for (int dd = 0; dd < DH; dd++)
                s += qs[r][hh * DH + dd] * g_wer[e * DM + hh * DH + dd];
            g_QW[(i0 + r) * 64 + c] = s;
        }
    }
}

// ---------- kernel 3: fused attention, j-split ----------
__global__ __launch_bounds__(512, 2)
void attn_kernel(const int* __restrict__ adj, const float* __restrict__ edge) {
    extern __shared__ float sm[];
    float* Qs   = sm;                       // 2048
    float* QWs  = Qs + BI * DM;             // 1024
    float* sc   = QWs + BI * 64;            // 4096
    float* Ks   = sc + HH * BI * TJ;        // 5120
    float* Vs   = Ks + HH * TJ * KSTR;      // 5120
    int*   adjs = (int*)(Vs + HH * TJ * KSTR);  // 512
    float* lred = (float*)(adjs + BI * TJ);     // 512
    float* red  = Ks;                       // aliases Ks/Vs for final reduce

    const int tid = threadIdx.x;
    const int i0 = blockIdx.x * BI;
    const int split = blockIdx.y;
    const int jbase = split * (NN / NSPLIT);

    for (int t = tid; t < BI * DM; t += 512) Qs[t] = g_Q[i0 * DM + t];
    for (int t = tid; t < BI * 64; t += 512) QWs[t] = g_QW[i0 * 64 + t];

    const int p1_i = tid >> 5, p1_j = tid & 31;
    const int p2_h = tid >> 6, p2_j = (tid >> 1) & 31, p2_ih = tid & 1;
    const int p3_h = tid >> 6, p3_iq = (tid >> 4) & 3,
              p3_dq = (tid >> 2) & 3, p3_jq = tid & 3;

    u64 acc2[4][2];
    #pragma unroll
    for (int a = 0; a < 4; a++) { acc2[a][0] = 0ull; acc2[a][1] = 0ull; }
    float lp[4] = {0.f, 0.f, 0.f, 0.f};

    __syncthreads();

    for (int tix = 0; tix < JT_PER; tix++) {
        const int jt = jbase + tix * TJ;
        // ---- stage K, V tiles + adj ----
        {
            const float4* K4 = (const float4*)g_Kh;
            const float4* V4 = (const float4*)g_Vh;
            #pragma unroll
            for (int t4 = tid; t4 < HH * TJ * 4; t4 += 512) {
                int h = t4 >> 7, jj = (t4 >> 2) & 31, d4 = t4 & 3;
                float4 kv = K4[h * (NN * 4) + (jt + jj) * 4 + d4];
                *(float4*)&Ks[(h * TJ + jj) * KSTR + d4 * 4] = kv;
                float4 vv = V4[h * (NN * 4) + (jt + jj) * 4 + d4];
                *(float4*)&Vs[(h * TJ + jj) * KSTR + d4 * 4] = vv;
            }
            adjs[tid] = adj[(size_t)(i0 + (tid >> 5)) * NN + jt + (tid & 31)];
        }
        __syncthreads();

        // ---- phase 1: edge bias for all 8 heads (packed f32x2) ----
        {
            const ulonglong2* ep = (const ulonglong2*)(edge +
                ((size_t)(i0 + p1_i) * NN + (size_t)(jt + p1_j)) * ED);
            ulonglong2 E01 = ep[0];   // pairs (e0,e1),(e2,e3)
            ulonglong2 E23 = ep[1];   // pairs (e4,e5),(e6,e7)
            const float* qwb = QWs + p1_i * 64;
            #pragma unroll
            for (int h = 0; h < 8; h++) {
                ulonglong2 w01 = *(const ulonglong2*)(qwb + h * 8);
                ulonglong2 w23 = *(const ulonglong2*)(qwb + h * 8 + 4);
                u64 t0 = f2_mul(w01.x, E01.x);
                u64 t1 = f2_mul(w01.y, E01.y);
                t0 = f2_fma(w23.x, E23.x, t0);
                t1 = f2_fma(w23.y, E23.y, t1);
                sc[(h * BI + p1_i) * TJ + p1_j] = f2_red(f2_add(t0, t1));
            }
        }
        __syncthreads();

        // ---- phase 2: QK + leaky-relu + mask + exp (packed f32x2) ----
        {
            const ulonglong2* kp = (const ulonglong2*)&Ks[(p2_h * TJ + p2_j) * KSTR];
            ulonglong2 k0 = kp[0], k1 = kp[1], k2 = kp[2], k3 = kp[3];
            #pragma unroll
            for (int ii = 0; ii < 8; ii++) {
                int i = p2_ih * 8 + ii;
                const ulonglong2* qp = (const ulonglong2*)&Qs[i * DM + p2_h * DH];
                ulonglong2 q0 = qp[0], q1 = qp[1], q2 = qp[2], q3 = qp[3];
                u64 t0 = f2_mul(q0.x, k0.x);
                u64 t1 = f2_mul(q0.y, k0.y);
                t0 = f2_fma(q1.x, k1.x, t0);
                t1 = f2_fma(q1.y, k1.y, t1);
                t0 = f2_fma(q2.x, k2.x, t0);
                t1 = f2_fma(q2.y, k2.y, t1);
                t0 = f2_fma(q3.x, k3.x, t0);
                t1 = f2_fma(q3.y, k3.y, t1);
                float s = f2_red(f2_add(t0, t1));
                int idx = (p2_h * BI + i) * TJ + p2_j;
                s = (s + sc[idx]) * 0.25f;
                s = (s > 0.f) ? s : 0.2f * s;
                float p = (adjs[i * TJ + p2_j] != 0) ? __expf(s) : 0.f;
                sc[idx] = p;
            }
        }
        __syncthreads();

        // ---- phase 3: accumulate P @ V (packed f32x2) ----
        {
            #pragma unroll
            for (int jj = 0; jj < 8; jj++) {
                int j = p3_jq * 8 + jj;
                ulonglong2 v = *(const ulonglong2*)&Vs[(p3_h * TJ + j) * KSTR + p3_dq * 4];
                #pragma unroll
                for (int ii = 0; ii < 4; ii++) {
                    float p = sc[(p3_h * BI + p3_iq * 4 + ii) * TJ + j];
                    u64 pp = f2_pack(p, p);
                    acc2[ii][0] = f2_fma(pp, v.x, acc2[ii][0]);
                    acc2[ii][1] = f2_fma(pp, v.y, acc2[ii][1]);
                    if (p3_dq == 0) lp[ii] += p;
                }
            }
        }
        __syncthreads();
    }

    // ---- final reductions across jq slices ----
    if (p3_dq == 0) {
        #pragma unroll
        for (int ii = 0; ii < 4; ii++)
            lred[(p3_h * BI + p3_iq * 4 + ii) * 4 + p3_jq] = lp[ii];
    }
    #pragma unroll
    for (int ii = 0; ii < 4; ii++) {
        float a0, a1, a2, a3;
        f2_unpack(acc2[ii][0], a0, a1);
        f2_unpack(acc2[ii][1], a2, a3);
        red[tid * 16 + ii * 4 + 0] = a0;
        red[tid * 16 + ii * 4 + 1] = a1;
        red[tid * 16 + ii * 4 + 2] = a2;
        red[tid * 16 + ii * 4 + 3] = a3;
    }
    __syncthreads();

    if (p3_jq == 0) {
        #pragma unroll
        for (int ii = 0; ii < 4; ii++) {
            int i = p3_iq * 4 + ii;
            if (p3_dq == 0) {
                int lb = (p3_h * BI + i) * 4;
                g_lsum[(split * NN + i0 + i) * HH + p3_h] =
                    lred[lb] + lred[lb + 1] + lred[lb + 2] + lred[lb + 3];
            }
            #pragma unroll
            for (int dd = 0; dd < 4; dd++) {
                float s = red[(tid + 0) * 16 + ii * 4 + dd]
                        + red[(tid + 1) * 16 + ii * 4 + dd]
                        + red[(tid + 2) * 16 + ii * 4 + dd]
                        + red[(tid + 3) * 16 + ii * 4 + dd];
                g_part[((size_t)split * NN + i0 + i) * DM + p3_h * DH + p3_dq * 4 + dd] = s;
            }
        }
    }
}

// ---------- kernel 4: combine partials, normalize, @ Wo ----------
__global__ __launch_bounds__(128)
void combine_kernel(const float* __restrict__ Wo, float* __restrict__ out) {
    __shared__ float xs[8][DM];
    const int i0 = blockIdx.x * 8;
    const int c = threadIdx.x;
    const int h = c >> 4;
    #pragma unroll
    for (int r = 0; r < 8; r++) {
        int i = i0 + r;
        float s = 0.f, l = 0.f;
        #pragma unroll
        for (int sp = 0; sp < NSPLIT; sp++) {
            s += g_part[((size_t)sp * NN + i) * DM + c];
            l += g_lsum[(sp * NN + i) * HH + h];
        }
        xs[r][c] = s / l;
    }
    __syncthreads();
    float a[8] = {0.f, 0.f, 0.f, 0.f, 0.f, 0.f, 0.f, 0.f};
    for (int d = 0; d < DM; d++) {
        float w = Wo[d * DM + c];
        #pragma unroll
        for (int r = 0; r < 8; r++) a[r] += xs[r][d] * w;
    }
    #pragma unroll
    for (int r = 0; r < 8; r++) out[(i0 + r) * DM + c] = a[r];
}

// ---------- launch ----------
extern "C" void kernel_launch(void* const* d_in, const int* in_sizes, int n_in,
                              void* d_out, int out_size) {
    const float* X    = (const float*)d_in[0];
    const int*   adj  = (const int*)  d_in[1];
    const float* edge = (const float*)d_in[2];
    const float* Wq   = (const float*)d_in[3];
    const float* Wk   = (const float*)d_in[4];
    const float* Wv   = (const float*)d_in[5];
    const float* We   = (const float*)d_in[6];
    const float* Wr   = (const float*)d_in[7];
    const float* Wo   = (const float*)d_in[8];
    float* out = (float*)d_out;

    const int smem_bytes = (BI*DM + BI*64 + HH*BI*TJ + 2*HH*TJ*KSTR + BI*TJ + 512) * 4;
    cudaFuncSetAttribute(attn_kernel, cudaFuncAttributeMaxDynamicSharedMemorySize, smem_bytes);

    wer_kernel<<<1, 128>>>(We, Wr);
    proj_kernel<<<NN / 8, 128>>>(X, Wq, Wk, Wv);
    attn_kernel<<<dim3(NN / BI, NSPLIT), 512, smem_bytes>>>(adj, edge);
    combine_kernel<<<NN / 8, 128>>>(Wo, out);
}

// round 3
// speedup vs baseline: 1.4474x; 1.4050x over previous
#include <cuda_runtime.h>
#include <cstddef>

#define NN 2048
#define DM 128
#define HH 8
#define DH 16
#define ED 8

#define BI 16
#define TJ 32
#define NSPLIT 32
#define JRANGE (NN / NSPLIT)   // 64
#define KSTR 20                // padded K row stride (floats)
#define SCSTR 33               // padded score row stride (floats)

// ---------- packed f32x2 helpers ----------
using u64 = unsigned long long;
__device__ __forceinline__ u64 f2_pack(float lo, float hi) {
    u64 r; asm("mov.b64 %0, {%1,%2};" : "=l"(r) : "f"(lo), "f"(hi)); return r;
}
__device__ __forceinline__ u64 f2_mul(u64 a, u64 b) {
    u64 d; asm("mul.rn.f32x2 %0, %1, %2;" : "=l"(d) : "l"(a), "l"(b)); return d;
}
__device__ __forceinline__ u64 f2_fma(u64 a, u64 b, u64 c) {
    u64 d; asm("fma.rn.f32x2 %0, %1, %2, %3;" : "=l"(d) : "l"(a), "l"(b), "l"(c)); return d;
}
__device__ __forceinline__ u64 f2_add(u64 a, u64 b) {
    u64 d; asm("add.rn.f32x2 %0, %1, %2;" : "=l"(d) : "l"(a), "l"(b)); return d;
}
__device__ __forceinline__ float f2_red(u64 a) {
    float lo, hi; asm("mov.b64 {%0,%1}, %2;" : "=f"(lo), "=f"(hi) : "l"(a)); return lo + hi;
}
__device__ __forceinline__ void f2_unpack(u64 a, float& lo, float& hi) {
    asm("mov.b64 {%0,%1}, %2;" : "=f"(lo), "=f"(hi) : "l"(a));
}

// ---------- device scratch ----------
__device__ float g_wer[ED * DM];
__device__ float g_Q  [NN * DM];
__device__ float g_Kh [NN * DM];               // [h][j][16]
__device__ float g_Vh [NN * DM];               // [h][j][16]
__device__ float g_QW [NN * HH * ED];          // [i][h*8+e]
__device__ float g_part[(size_t)NSPLIT * NN * DM];
__device__ float g_lsum[NSPLIT * NN * HH];
__device__ float g_O  [NN * DM];

// ---------- kernel 1: Wer = We @ Wr ----------
__global__ void wer_kernel(const float* __restrict__ We, const float* __restrict__ Wr) {
    int c = threadIdx.x;
    for (int e = 0; e < ED; e++) {
        float s = 0.f;
        #pragma unroll 8
        for (int k = 0; k < 32; k++) s += We[e * 32 + k] * Wr[k * DM + c];
        g_wer[e * DM + c] = s;
    }
}

// ---------- kernel 2: projections (smem-chunked weights) ----------
#define PCH 16
__global__ __launch_bounds__(128)
void proj_kernel(const float* __restrict__ X,
                 const float* __restrict__ Wq,
                 const float* __restrict__ Wk,
                 const float* __restrict__ Wv) {
    __shared__ float xs[8][DM];
    __shared__ float qs[8][DM];
    __shared__ float ws[3][PCH][DM];
    const int i0 = blockIdx.x * 8;
    const int c = threadIdx.x;

    #pragma unroll
    for (int r = 0; r < 8; r++) xs[r][c] = X[(i0 + r) * DM + c];

    float qa[8], ka[8], va[8];
    #pragma unroll
    for (int r = 0; r < 8; r++) { qa[r] = 0.f; ka[r] = 0.f; va[r] = 0.f; }

    for (int ch = 0; ch < DM / PCH; ch++) {
        const int d0 = ch * PCH;
        __syncthreads();
        // cooperative load of 3 x PCH x 128 weight rows (float4)
        #pragma unroll
        for (int s = 0; s < 3 * PCH * 32 / 128; s++) {
            int t = c + s * 128;
            int m = t / (PCH * 32);
            int rem = t % (PCH * 32);
            int dd = rem >> 5, c4 = rem & 31;
            const float* Wm = (m == 0) ? Wq : (m == 1) ? Wk : Wv;
            *(float4*)&ws[m][dd][c4 * 4] = *(const float4*)&Wm[(d0 + dd) * DM + c4 * 4];
        }
        __syncthreads();
        #pragma unroll
        for (int dd = 0; dd < PCH; dd++) {
            float wq = ws[0][dd][c];
            float wk = ws[1][dd][c];
            float wv = ws[2][dd][c];
            #pragma unroll
            for (int r = 0; r < 8; r++) {
                float x = xs[r][d0 + dd];
                qa[r] += x * wq;
                ka[r] += x * wk;
                va[r] += x * wv;
            }
        }
    }
    const int h = c >> 4, d = c & 15;
    #pragma unroll
    for (int r = 0; r < 8; r++) {
        g_Q[(i0 + r) * DM + c] = qa[r];
        qs[r][c] = qa[r];
        g_Kh[(h * NN + i0 + r) * DH + d] = ka[r];
        g_Vh[(h * NN + i0 + r) * DH + d] = va[r];
    }
    __syncthreads();
    if (c < 64) {
        const int hh = c >> 3, e = c & 7;
        #pragma unroll
        for (int r = 0; r < 8; r++) {
            float s = 0.f;
            #pragma unroll
            for (int dd = 0; dd < DH; dd++)
                s += qs[r][hh * DH + dd] * g_wer[e * DM + hh * DH + dd];
            g_QW[(i0 + r) * 64 + c] = s;
        }
    }
}

// ---------- kernel 3: fused attention, warp-private mainloop ----------
__global__ __launch_bounds__(512, 2)
void attn_kernel(const int* __restrict__ adj, const float* __restrict__ edge) {
    extern __shared__ float sm[];
    float* Qs   = sm;                          // [i][128]      2048
    float* QWs  = Qs + BI * DM;                // [i][64]       1024
    float* sc   = QWs + BI * 64;               // [h][i][33]    4224
    float* Ks   = sc + HH * BI * SCSTR;        // [h][jj][20]  10240
    float* Vs   = Ks + HH * JRANGE * KSTR;     // [h][jj][16]   8192
    int*   adjs = (int*)(Vs + HH * JRANGE * 16);   // [i][32]    512

    const int tid = threadIdx.x;
    const int i0 = blockIdx.x * BI;
    const int split = blockIdx.y;
    const int jbase = split * JRANGE;

    // ---- one-time staging ----
    for (int t = tid; t < BI * DM; t += 512) Qs[t] = g_Q[i0 * DM + t];
    for (int t = tid; t < BI * 64; t += 512) QWs[t] = g_QW[i0 * 64 + t];
    {
        const float4* K4 = (const float4*)g_Kh;
        const float4* V4 = (const float4*)g_Vh;
        #pragma unroll
        for (int s = 0; s < HH * JRANGE * 4 / 512; s++) {
            int t4 = tid + s * 512;
            int h = t4 >> 8, jj = (t4 >> 2) & 63, d4 = t4 & 3;
            float4 kv = K4[(h * NN + jbase + jj) * 4 + d4];
            *(float4*)&Ks[(h * JRANGE + jj) * KSTR + d4 * 4] = kv;
            float4 vv = V4[(h * NN + jbase + jj) * 4 + d4];
            *(float4*)&Vs[(h * JRANGE + jj) * 16 + d4 * 4] = vv;
        }
    }

    // role ids
    const int p1_i = tid >> 5, p1_j = tid & 31;         // phase 1: (i, j)
    const int w = tid >> 5, lane = tid & 31;
    const int h = w >> 1, u = w & 1;                    // warp = (head, i-octet)
    const int io = lane >> 2, dq = lane & 3;            // phase 3 roles

    // prefetch tile 0 edge + adj into registers
    const float* eb = edge + ((size_t)(i0 + p1_i) * NN + jbase + p1_j) * ED;
    ulonglong2 E01 = *(const ulonglong2*)eb;
    ulonglong2 E23 = *(const ulonglong2*)(eb + 4);
    int av = adj[(size_t)(i0 + p1_i) * NN + jbase + p1_j];

    u64 acc0 = 0ull, acc1 = 0ull;
    float lp = 0.f;

    __syncthreads();   // staging done

    #pragma unroll
    for (int t = 0; t < JRANGE / TJ; t++) {
        // ---- phase 1: edge bias for all 8 heads (regs -> sc) ----
        {
            const float* qwb = QWs + p1_i * 64;
            #pragma unroll
            for (int hh = 0; hh < 8; hh++) {
                ulonglong2 w01 = *(const ulonglong2*)(qwb + hh * 8);
                ulonglong2 w23 = *(const ulonglong2*)(qwb + hh * 8 + 4);
                u64 t0 = f2_mul(w01.x, E01.x);
                u64 t1 = f2_mul(w01.y, E01.y);
                t0 = f2_fma(w23.x, E23.x, t0);
                t1 = f2_fma(w23.y, E23.y, t1);
                sc[(hh * BI + p1_i) * SCSTR + p1_j] = f2_red(f2_add(t0, t1));
            }
            adjs[p1_i * TJ + p1_j] = av;
        }
        __syncthreads();   // sc/adjs ready

        // prefetch next tile's edge+adj (latency hidden by phase 2/3)
        if (t + 1 < JRANGE / TJ) {
            const float* eb1 = edge +
                ((size_t)(i0 + p1_i) * NN + jbase + (t + 1) * TJ + p1_j) * ED;
            E01 = *(const ulonglong2*)eb1;
            E23 = *(const ulonglong2*)(eb1 + 4);
            av = adj[(size_t)(i0 + p1_i) * NN + jbase + (t + 1) * TJ + p1_j];
        }

        // ---- phase 2: QK + bias + leaky + mask + exp (lane = j) ----
        {
            const ulonglong2* kp =
                (const ulonglong2*)&Ks[(h * JRANGE + t * TJ + lane) * KSTR];
            ulonglong2 k0 = kp[0], k1 = kp[1], k2 = kp[2], k3 = kp[3];
            #pragma unroll
            for (int ii = 0; ii < 8; ii++) {
                int i = u * 8 + ii;
                const ulonglong2* qp = (const ulonglong2*)&Qs[i * DM + h * DH];
                ulonglong2 q0 = qp[0], q1 = qp[1], q2 = qp[2], q3 = qp[3];
                u64 t0 = f2_mul(q0.x, k0.x);
                u64 t1 = f2_mul(q0.y, k0.y);
                t0 = f2_fma(q1.x, k1.x, t0);
                t1 = f2_fma(q1.y, k1.y, t1);
                t0 = f2_fma(q2.x, k2.x, t0);
                t1 = f2_fma(q2.y, k2.y, t1);
                t0 = f2_fma(q3.x, k3.x, t0);
                t1 = f2_fma(q3.y, k3.y, t1);
                float s = f2_red(f2_add(t0, t1));
                int idx = (h * BI + i) * SCSTR + lane;
                s = (s + sc[idx]) * 0.25f;
                s = fmaxf(s, 0.2f * s);                 // leaky relu
                float p = (adjs[i * TJ + lane] != 0) ? __expf(s) : 0.f;
                sc[idx] = p;                            // overwrite bias with p
            }
        }
        __syncwarp();

        // ---- phase 3: PV accumulate, fully lane-resident (lane = (io,dq)) ----
        {
            const int i = u * 8 + io;
            const float* pb = &sc[(h * BI + i) * SCSTR];
            const float* vb = &Vs[(h * JRANGE + t * TJ) * 16 + dq * 4];
            #pragma unroll
            for (int j = 0; j < TJ; j++) {
                float p = pb[j];
                ulonglong2 v = *(const ulonglong2*)(vb + j * 16);
                u64 pp = f2_pack(p, p);
                acc0 = f2_fma(pp, v.x, acc0);
                acc1 = f2_fma(pp, v.y, acc1);
                lp += p;
            }
        }
        __syncthreads();   // sc consumed, reusable next tile
    }

    // ---- direct store: no cross-lane reduction needed ----
    {
        const int i = u * 8 + io;
        float a0, a1, a2, a3;
        f2_unpack(acc0, a0, a1);
        f2_unpack(acc1, a2, a3);
        *(float4*)&g_part[((size_t)split * NN + i0 + i) * DM + h * DH + dq * 4] =
            make_float4(a0, a1, a2, a3);
        if (dq == 0)
            g_lsum[(split * NN + i0 + i) * HH + h] = lp;
    }
}

// ---------- kernel 4: reduce partials + normalize ----------
__global__ __launch_bounds__(256)
void reduce_kernel() {
    int idx = blockIdx.x * 256 + threadIdx.x;   // (i, c4)
    int i = idx >> 5, c4 = idx & 31;
    int h = c4 >> 2;
    float4 s = make_float4(0.f, 0.f, 0.f, 0.f);
    float l = 0.f;
    #pragma unroll
    for (int sp = 0; sp < NSPLIT; sp++) {
        float4 v = *(const float4*)&g_part[((size_t)sp * NN + i) * DM + c4 * 4];
        s.x += v.x; s.y += v.y; s.z += v.z; s.w += v.w;
        l += g_lsum[(sp * NN + i) * HH + h];
    }
    float inv = 1.f / l;
    s.x *= inv; s.y *= inv; s.z *= inv; s.w *= inv;
    *(float4*)&g_O[i * DM + c4 * 4] = s;
}

// ---------- kernel 5: out = O @ Wo (Wo staged in smem) ----------
__global__ __launch_bounds__(128)
void outproj_kernel(const float* __restrict__ Wo, float* __restrict__ out) {
    __shared__ float xs[4][DM];
    __shared__ float ws[PCH][DM];
    const int i0 = blockIdx.x * 4;
    const int c = threadIdx.x;
    #pragma unroll
    for (int r = 0; r < 4; r++) xs[r][c] = g_O[(i0 + r) * DM + c];
    float a[4] = {0.f, 0.f, 0.f, 0.f};
    for (int ch = 0; ch < DM / PCH; ch++) {
        const int d0 = ch * PCH;
        __syncthreads();
        #pragma unroll
        for (int s = 0; s < PCH * 32 / 128; s++) {
            int t = c + s * 128;
            int dd = t >> 5, c4 = t & 31;
            *(float4*)&ws[dd][c4 * 4] = *(const float4*)&Wo[(d0 + dd) * DM + c4 * 4];
        }
        __syncthreads();
        #pragma unroll
        for (int dd = 0; dd < PCH; dd++) {
            float wv = ws[dd][c];
            #pragma unroll
            for (int r = 0; r < 4; r++) a[r] += xs[r][d0 + dd] * wv;
        }
    }
    #pragma unroll
    for (int r = 0; r < 4; r++) out[(i0 + r) * DM + c] = a[r];
}

// ---------- launch ----------
extern "C" void kernel_launch(void* const* d_in, const int* in_sizes, int n_in,
                              void* d_out, int out_size) {
    const float* X    = (const float*)d_in[0];
    const int*   adj  = (const int*)  d_in[1];
    const float* edge = (const float*)d_in[2];
    const float* Wq   = (const float*)d_in[3];
    const float* Wk   = (const float*)d_in[4];
    const float* Wv   = (const float*)d_in[5];
    const float* We   = (const float*)d_in[6];
    const float* Wr   = (const float*)d_in[7];
    const float* Wo   = (const float*)d_in[8];
    float* out = (float*)d_out;

    const int smem_bytes =
        (BI*DM + BI*64 + HH*BI*SCSTR + HH*JRANGE*KSTR + HH*JRANGE*16 + BI*TJ) * 4;
    cudaFuncSetAttribute(attn_kernel, cudaFuncAttributeMaxDynamicSharedMemorySize, smem_bytes);

    wer_kernel<<<1, 128>>>(We, Wr);
    proj_kernel<<<NN / 8, 128>>>(X, Wq, Wk, Wv);
    attn_kernel<<<dim3(NN / BI, NSPLIT), 512, smem_bytes>>>(adj, edge);
    reduce_kernel<<<NN * 32 / 256, 256>>>();
    outproj_kernel<<<NN / 4, 128>>>(Wo, out);
}